// round 17
// baseline (speedup 1.0000x reference)
#include <cuda_runtime.h>
#include <cuda_bf16.h>
#include <math.h>

#define NN 131072
#define EE 2097152
#define DD 64
#define LL 3
#define RR 3
#define NBASE 2
#define BB 4096

// ---------------- device scratch (no allocs; zero-initialized at load) ----------------
// W layout: [conv][col][96 words]; word widx: chunk=widx>>5, t=widx&31, ks=t>>3,
// q=(t>>1)&3, u=t&1 -> k-pair = chunk*32 + ks*8 + q + 4u (B-fragment words adjacent)
__device__ unsigned g_WkH[6 * 64 * 96];     // bf16x2 hi pairs
__device__ unsigned g_WkL[6 * 64 * 96];     // bf16x2 lo pairs
__device__ float g_Bpack[6 * DD];
__device__ float g_AGGB[(size_t)NN * 128];  // 2 basis accumulators (compacted rows when IDX)
__device__ float g_Hl[(size_t)NN * DD];
__device__ float g_Hg0[(size_t)NN * DD];
__device__ float g_Hg1[(size_t)NN * DD];
__device__ float g_Hg2[(size_t)NN * DD];
// CSR + frontier structures (graph identical for all 6 convs)
__device__ int    g_cnt[NN];    // zeroed by k34 each call (zero-init on load)
__device__ int    g_flag[NN];   // zeroed by k34 each call
__device__ int    g_cur[NN];
__device__ int    g_rowptr[NN + 1];
__device__ int    g_se2[EE];            // src*64 in CSR order
__device__ float2 g_wab[6 * (size_t)EE]; // per-conv (wa, wb) = norm * C[etype][b]
__device__ int    g_blksum[512];
__device__ int    g_fsum[512];
__device__ int    g_list[NN];
__device__ int    g_nfront;

__device__ __forceinline__ unsigned smem_u32(const void* p) {
    unsigned a;
    asm("{ .reg .u64 t; cvta.to.shared.u64 t, %1; cvt.u32.u64 %0, t; }" : "=r"(a) : "l"(p));
    return a;
}
__device__ __forceinline__ void cp16(unsigned saddr, const void* g) {
    asm volatile("cp.async.cg.shared.global [%0], [%1], 16;" :: "r"(saddr), "l"(g) : "memory");
}
#define CP_COMMIT() asm volatile("cp.async.commit_group;" ::: "memory")
#define CP_WAIT(n)  asm volatile("cp.async.wait_group %0;" :: "n"(n) : "memory")

// ---------------- K1: count (CSR histogram) + frontier mark + weight prep (bf16 split) ----
#define COUNT_BLOCKS (EE / 256)          // 8192
#define PREP_ITEMS   (6 * 64 * 96)       // 36864
#define PREP_BLOCKS  ((PREP_ITEMS + 255) / 256)

__global__ void k1_combo(const int* __restrict__ src, const int* __restrict__ dst,
                         const float* __restrict__ lV, const float* __restrict__ lW,
                         const float* __restrict__ lB,
                         const float* __restrict__ gV, const float* __restrict__ gW,
                         const float* __restrict__ gB) {
    int b = blockIdx.x;
    if (b < COUNT_BLOCKS) {
        int e = b * 256 + threadIdx.x;
        int d = dst[e];
        atomicAdd(&g_cnt[d], 1);
        if (e < BB) g_flag[e] = 1;          // subgraph center nodes
        if (d < BB) g_flag[src[e]] = 1;     // srcs feeding the subgraph
        return;
    }
    int idx = (b - COUNT_BLOCKS) * 256 + threadIdx.x;
    if (idx >= PREP_ITEMS) return;
    int c    = idx / (64 * 96);
    int rem  = idx % (64 * 96);
    int col  = rem / 96;
    int widx = rem % 96;
    int chunk = widx >> 5;
    int t     = widx & 31;
    int ks    = t >> 3;
    int qq    = (t >> 1) & 3;
    int u     = t & 1;
    int kp    = chunk * 32 + ks * 8 + qq + 4 * u;   // global k-pair index
    int layer = c >> 1;
    bool local = ((c & 1) == 0);
    const float* V = local ? lV : gV;
    const float* W = local ? lW : gW;
    const float* B = local ? lB : gB;

    float w[2];
    #pragma unroll
    for (int uu = 0; uu < 2; uu++) {
        int row = 2 * kp + uu;
        if (row < 128) {
            int bb = row >> 6, d = row & 63;
            w[uu] = V[(((size_t)layer * NBASE + bb) * DD + d) * DD + col];
        } else {
            int d = row - 128;
            w[uu] = W[((size_t)layer * DD + d) * DD + col];
        }
    }
    __nv_bfloat162 hi2 = __float22bfloat162_rn(make_float2(w[0], w[1]));
    unsigned uh = *(unsigned*)&hi2;
    float r0 = w[0] - __uint_as_float(uh << 16);
    float r1 = w[1] - __uint_as_float(uh & 0xFFFF0000u);
    __nv_bfloat162 lo2 = __float22bfloat162_rn(make_float2(r0, r1));
    g_WkH[idx] = uh;
    g_WkL[idx] = *(unsigned*)&lo2;
    if (widx == 0) g_Bpack[c * DD + col] = B[layer * DD + col];
}

// ---------------- K2: per-block partial sums of cnt and flag ----------------
__global__ void k2_partial2() {
    __shared__ int s[256];
    int tid = threadIdx.x;
    int i = blockIdx.x * 256 + tid;
    s[tid] = g_cnt[i];
    __syncthreads();
    #pragma unroll
    for (int d = 128; d > 0; d >>= 1) {
        if (tid < d) s[tid] += s[tid + d];
        __syncthreads();
    }
    if (tid == 0) g_blksum[blockIdx.x] = s[0];
    __syncthreads();
    s[tid] = g_flag[i];
    __syncthreads();
    #pragma unroll
    for (int d = 128; d > 0; d >>= 1) {
        if (tid < d) s[tid] += s[tid + d];
        __syncthreads();
    }
    if (tid == 0) g_fsum[blockIdx.x] = s[0];
}

// ---------------- K34: per-block prefix over blksums + write rowptr/cur + compact ------
__global__ void k34_write() {
    __shared__ int s[256];
    __shared__ int base_c, base_f;
    int tid = threadIdx.x;
    int b = blockIdx.x;
    // base_c = sum of blksum[p] for p < b  (each thread covers p = tid and tid+256)
    int v = ((tid < b) ? g_blksum[tid] : 0) + ((tid + 256 < b) ? g_blksum[tid + 256] : 0);
    s[tid] = v;
    __syncthreads();
    #pragma unroll
    for (int d = 128; d > 0; d >>= 1) {
        if (tid < d) s[tid] += s[tid + d];
        __syncthreads();
    }
    if (tid == 0) base_c = s[0];
    __syncthreads();
    int vf = ((tid < b) ? g_fsum[tid] : 0) + ((tid + 256 < b) ? g_fsum[tid + 256] : 0);
    s[tid] = vf;
    __syncthreads();
    #pragma unroll
    for (int d = 128; d > 0; d >>= 1) {
        if (tid < d) s[tid] += s[tid + d];
        __syncthreads();
    }
    if (tid == 0) base_f = s[0];
    __syncthreads();

    int i = b * 256 + tid;
    int cv = g_cnt[i];
    s[tid] = cv;
    __syncthreads();
    #pragma unroll
    for (int d = 1; d < 256; d <<= 1) {
        int t = (tid >= d) ? s[tid - d] : 0;
        __syncthreads();
        s[tid] += t;
        __syncthreads();
    }
    int pos = base_c + s[tid] - cv;
    g_rowptr[i] = pos;
    g_cur[i] = pos;
    g_cnt[i] = 0;
    if (i == NN - 1) g_rowptr[NN] = EE;
    __syncthreads();
    int fv = g_flag[i];
    s[tid] = fv;
    __syncthreads();
    #pragma unroll
    for (int d = 1; d < 256; d <<= 1) {
        int t = (tid >= d) ? s[tid - d] : 0;
        __syncthreads();
        s[tid] += t;
        __syncthreads();
    }
    int fpos = base_f + s[tid] - fv;
    if (fv) g_list[fpos] = i;
    g_flag[i] = 0;
    if (i == NN - 1) g_nfront = fpos + fv;
}

// ---------------- K5: fill CSR payload (se + per-conv precomputed weights) -------------
__global__ void k5_fill(const int* __restrict__ src, const int* __restrict__ dst,
                        const int* __restrict__ etype,
                        const float* __restrict__ mask, const float* __restrict__ mask2,
                        const float* __restrict__ lC, const float* __restrict__ gC) {
    int e = blockIdx.x * blockDim.x + threadIdx.x;
    if (e >= EE) return;
    int d = dst[e];
    int et = etype[e];
    int pos = atomicAdd(&g_cur[d], 1);
    g_se2[pos] = src[e] * DD;
    float m1 = mask[e];
    float m2 = mask2[e];
    #pragma unroll
    for (int layer = 0; layer < LL; layer++) {
        float cl0 = __ldg(lC + layer * RR * NBASE + et * NBASE + 0);
        float cl1 = __ldg(lC + layer * RR * NBASE + et * NBASE + 1);
        float cg0 = __ldg(gC + layer * RR * NBASE + et * NBASE + 0);
        float cg1 = __ldg(gC + layer * RR * NBASE + et * NBASE + 1);
        g_wab[(size_t)(2 * layer) * EE + pos]     = make_float2(m1 * cl0, m1 * cl1);
        g_wab[(size_t)(2 * layer + 1) * EE + pos] = make_float2(m2 * cg0, m2 * cg1);
    }
}

// ---------------- basis gather: 16 lanes/node, 4-edge unroll, precomputed weights ------
template <bool IDX>
__global__ __launch_bounds__(256)
void gather2_kernel(const float* __restrict__ h, const int* __restrict__ se,
                    const float2* __restrict__ wab, int nNodes) {
    int t = blockIdx.x * blockDim.x + threadIdx.x;
    int li = t >> 4;
    int lane = t & 15;
    int limit = IDX ? g_nfront : nNodes;
    if (li >= limit) return;
    int node = IDX ? g_list[li] : li;

    int e0 = g_rowptr[node];
    int e1 = g_rowptr[node + 1];
    float4 a0 = make_float4(0.f, 0.f, 0.f, 0.f);
    float4 a1 = make_float4(0.f, 0.f, 0.f, 0.f);
    int e = e0;
    #pragma unroll 1
    for (; e + 4 <= e1; e += 4) {
        int s0 = __ldg(&se[e]),     s1 = __ldg(&se[e + 1]);
        int s2 = __ldg(&se[e + 2]), s3 = __ldg(&se[e + 3]);
        float2 w0 = __ldcs(&wab[e]);
        float2 w1 = __ldcs(&wab[e + 1]);
        float2 w2 = __ldcs(&wab[e + 2]);
        float2 w3 = __ldcs(&wab[e + 3]);
        float4 h0 = *(const float4*)(h + s0 + lane * 4);
        float4 h1 = *(const float4*)(h + s1 + lane * 4);
        float4 h2 = *(const float4*)(h + s2 + lane * 4);
        float4 h3 = *(const float4*)(h + s3 + lane * 4);
        a0.x = fmaf(w0.x, h0.x, a0.x); a0.y = fmaf(w0.x, h0.y, a0.y);
        a0.z = fmaf(w0.x, h0.z, a0.z); a0.w = fmaf(w0.x, h0.w, a0.w);
        a1.x = fmaf(w0.y, h0.x, a1.x); a1.y = fmaf(w0.y, h0.y, a1.y);
        a1.z = fmaf(w0.y, h0.z, a1.z); a1.w = fmaf(w0.y, h0.w, a1.w);
        a0.x = fmaf(w1.x, h1.x, a0.x); a0.y = fmaf(w1.x, h1.y, a0.y);
        a0.z = fmaf(w1.x, h1.z, a0.z); a0.w = fmaf(w1.x, h1.w, a0.w);
        a1.x = fmaf(w1.y, h1.x, a1.x); a1.y = fmaf(w1.y, h1.y, a1.y);
        a1.z = fmaf(w1.y, h1.z, a1.z); a1.w = fmaf(w1.y, h1.w, a1.w);
        a0.x = fmaf(w2.x, h2.x, a0.x); a0.y = fmaf(w2.x, h2.y, a0.y);
        a0.z = fmaf(w2.x, h2.z, a0.z); a0.w = fmaf(w2.x, h2.w, a0.w);
        a1.x = fmaf(w2.y, h2.x, a1.x); a1.y = fmaf(w2.y, h2.y, a1.y);
        a1.z = fmaf(w2.y, h2.z, a1.z); a1.w = fmaf(w2.y, h2.w, a1.w);
        a0.x = fmaf(w3.x, h3.x, a0.x); a0.y = fmaf(w3.x, h3.y, a0.y);
        a0.z = fmaf(w3.x, h3.z, a0.z); a0.w = fmaf(w3.x, h3.w, a0.w);
        a1.x = fmaf(w3.y, h3.x, a1.x); a1.y = fmaf(w3.y, h3.y, a1.y);
        a1.z = fmaf(w3.y, h3.z, a1.z); a1.w = fmaf(w3.y, h3.w, a1.w);
    }
    #pragma unroll 1
    for (; e < e1; e++) {
        int s = __ldg(&se[e]);
        float2 w = __ldcs(&wab[e]);
        float4 hv = *(const float4*)(h + s + lane * 4);
        a0.x = fmaf(w.x, hv.x, a0.x); a0.y = fmaf(w.x, hv.y, a0.y);
        a0.z = fmaf(w.x, hv.z, a0.z); a0.w = fmaf(w.x, hv.w, a0.w);
        a1.x = fmaf(w.y, hv.x, a1.x); a1.y = fmaf(w.y, hv.y, a1.y);
        a1.z = fmaf(w.y, hv.z, a1.z); a1.w = fmaf(w.y, hv.w, a1.w);
    }
    __stcs((float4*)(g_AGGB + (size_t)li * 128 + lane * 4), a0);
    __stcs((float4*)(g_AGGB + (size_t)li * 128 + 64 + lane * 4), a1);
}

// ---------------- stage-2 GEMM: bf16 2-way split mma.sync + cp.async double buffer -----
__device__ __forceinline__ void mma_bf16(float* c, const unsigned* a, const unsigned* b) {
    asm volatile(
        "mma.sync.aligned.m16n8k16.row.col.f32.bf16.bf16.f32 "
        "{%0,%1,%2,%3}, {%4,%5,%6,%7}, {%8,%9}, {%0,%1,%2,%3};"
        : "+f"(c[0]), "+f"(c[1]), "+f"(c[2]), "+f"(c[3])
        : "r"(a[0]), "r"(a[1]), "r"(a[2]), "r"(a[3]), "r"(b[0]), "r"(b[1]));
}

__device__ __forceinline__ void split_bf16(float2 v, unsigned& hi, unsigned& lo) {
    __nv_bfloat162 h2 = __float22bfloat162_rn(v);
    hi = *(unsigned*)&h2;
    float r0 = v.x - __uint_as_float(hi << 16);
    float r1 = v.y - __uint_as_float(hi & 0xFFFF0000u);
    __nv_bfloat162 l2 = __float22bfloat162_rn(make_float2(r0, r1));
    lo = *(unsigned*)&l2;
}

#define XS 68
#define WKP 40
#define OFF_AS(b)  ((b) * 128 * XS)
#define OFF_WH(b)  (2 * 128 * XS + (b) * 2 * 64 * WKP)
#define OFF_WL(b)  (OFF_WH(b) + 64 * WKP)
#define GEMM_SMEM ((2 * 128 * XS + 4 * 64 * WKP) * 4)

template <int ACT, bool IDX>   // ACT: 0 = ELU, 1 = leaky_relu(0.01)
__global__ __launch_bounds__(256, 2)
void gemm2_kernel(const float* __restrict__ h, int conv, float* __restrict__ Hout,
                  int nNodes) {
    extern __shared__ float smem[];
    __shared__ int snid[128];

    int limit = IDX ? g_nfront : nNodes;
    int row0 = blockIdx.x * 128;
    if (row0 >= limit) return;

    const unsigned* WpH = g_WkH + (size_t)conv * 64 * 96;
    const unsigned* WpL = g_WkL + (size_t)conv * 64 * 96;
    int tid = threadIdx.x;
    int warp = tid >> 5;
    int lane = tid & 31;
    int group = lane >> 2;
    int q     = lane & 3;
    unsigned sbase = smem_u32(smem);

    if (tid < 128) {
        int gr = row0 + tid;
        snid[tid] = IDX ? (gr < limit ? g_list[gr] : 0) : gr;
    }

    auto issue_chunk = [&](int chunk, int buf) {
        unsigned asb = sbase + OFF_AS(buf) * 4;
        #pragma unroll
        for (int it = 0; it < 8; it++) {
            int f = tid + it * 256;
            int row = f >> 4, k4 = f & 15;
            const float* g;
            if (chunk < 2)
                g = g_AGGB + (size_t)(row0 + row) * 128 + chunk * 64 + k4 * 4;
            else
                g = h + (size_t)snid[row] * DD + k4 * 4;
            cp16(asb + (unsigned)(row * XS + k4 * 4) * 4, g);
        }
        unsigned whb = sbase + OFF_WH(buf) * 4;
        unsigned wlb = sbase + OFF_WL(buf) * 4;
        #pragma unroll
        for (int it = 0; it < 2; it++) {
            int f = tid + it * 256;
            int col = f >> 3, w4 = f & 7;
            cp16(whb + (unsigned)(col * WKP + w4 * 4) * 4, WpH + col * 96 + chunk * 32 + w4 * 4);
            cp16(wlb + (unsigned)(col * WKP + w4 * 4) * 4, WpL + col * 96 + chunk * 32 + w4 * 4);
        }
        CP_COMMIT();
    };

    float acc[8][4];
    #pragma unroll
    for (int ni = 0; ni < 8; ni++)
        #pragma unroll
        for (int t = 0; t < 4; t++) acc[ni][t] = 0.f;

    issue_chunk(0, 0);
    __syncthreads();            // snid visible
    issue_chunk(1, 1);

    #pragma unroll
    for (int chunk = 0; chunk < 3; chunk++) {
        int buf = chunk == 2 ? 0 : chunk;
        if (chunk < 2) { CP_WAIT(1); } else { CP_WAIT(0); }
        __syncthreads();

        const float*    As  = smem + OFF_AS(buf);
        const unsigned* WsH = (const unsigned*)(smem + OFF_WH(buf));
        const unsigned* WsL = (const unsigned*)(smem + OFF_WL(buf));

        #pragma unroll
        for (int ks = 0; ks < 4; ks++) {
            int k0 = ks * 16;
            int kq = ks * 8 + q * 2;
            int rb = warp * 16 + group;
            float2 vA0 = *(const float2*)(As + rb * XS + k0 + 2 * q);
            float2 vA1 = *(const float2*)(As + (rb + 8) * XS + k0 + 2 * q);
            float2 vA2 = *(const float2*)(As + rb * XS + k0 + 2 * q + 8);
            float2 vA3 = *(const float2*)(As + (rb + 8) * XS + k0 + 2 * q + 8);
            unsigned aH[4], aL[4];
            split_bf16(vA0, aH[0], aL[0]);
            split_bf16(vA1, aH[1], aL[1]);
            split_bf16(vA2, aH[2], aL[2]);
            split_bf16(vA3, aH[3], aL[3]);
            #pragma unroll
            for (int ni = 0; ni < 8; ni++) {
                int cn = ni * 8 + group;
                uint2 bh = *(const uint2*)(WsH + cn * WKP + kq);
                uint2 bl = *(const uint2*)(WsL + cn * WKP + kq);
                unsigned bH[2] = { bh.x, bh.y };
                unsigned bL[2] = { bl.x, bl.y };
                mma_bf16(acc[ni], aH, bL);
                mma_bf16(acc[ni], aL, bH);
                mma_bf16(acc[ni], aH, bH);
            }
        }
        __syncthreads();
        if (chunk == 0) issue_chunk(2, 0);
    }

    // epilogue
    int r0 = row0 + warp * 16 + group;
    bool st0 = !IDX || (r0 < limit);
    bool st8 = !IDX || (r0 + 8 < limit);
    int nid0 = snid[warp * 16 + group];
    int nid8 = snid[warp * 16 + group + 8];
    #pragma unroll
    for (int ni = 0; ni < 8; ni++) {
        int cg = ni * 8 + 2 * q;
        float bv0 = g_Bpack[conv * DD + cg];
        float bv1 = g_Bpack[conv * DD + cg + 1];
        float v0 = acc[ni][0] + bv0, v1 = acc[ni][1] + bv1;
        float v2 = acc[ni][2] + bv0, v3 = acc[ni][3] + bv1;
        if (ACT == 0) {
            v0 = v0 > 0.f ? v0 : expm1f(v0);
            v1 = v1 > 0.f ? v1 : expm1f(v1);
            v2 = v2 > 0.f ? v2 : expm1f(v2);
            v3 = v3 > 0.f ? v3 : expm1f(v3);
        } else {
            v0 = v0 >= 0.f ? v0 : 0.01f * v0;
            v1 = v1 >= 0.f ? v1 : 0.01f * v1;
            v2 = v2 >= 0.f ? v2 : 0.01f * v2;
            v3 = v3 >= 0.f ? v3 : 0.01f * v3;
        }
        if (st0) *(float2*)(Hout + (size_t)nid0 * DD + cg) = make_float2(v0, v1);
        if (st8) *(float2*)(Hout + (size_t)nid8 * DD + cg) = make_float2(v2, v3);
    }
}

// ---------------- MLP head ----------------
__global__ void mlp_kernel(const float* __restrict__ w1, const float* __restrict__ b1,
                           const float* __restrict__ w2, const float* __restrict__ b2,
                           float* __restrict__ out) {
    __shared__ float sub[192];
    __shared__ float red[128];
    int n = blockIdx.x;
    int tid = threadIdx.x;
    if (tid < 64) {
        sub[tid]       = g_Hg0[(size_t)n * DD + tid];
        sub[64 + tid]  = g_Hg1[(size_t)n * DD + tid];
        sub[128 + tid] = g_Hg2[(size_t)n * DD + tid];
    }
    __syncthreads();
    float acc = b1[tid];
    const float* w1r = w1 + tid * 192;
    #pragma unroll 8
    for (int k = 0; k < 192; k++) acc += sub[k] * w1r[k];
    red[tid] = fmaxf(acc, 0.f) * w2[tid];
    __syncthreads();
    #pragma unroll
    for (int s = 64; s > 0; s >>= 1) {
        if (tid < s) red[tid] += red[tid + s];
        __syncthreads();
    }
    if (tid == 0) {
        float z = red[0] + b2[0];
        out[n] = 1.f / (1.f + expf(-z));
    }
}

// ---------------- launch ----------------
extern "C" void kernel_launch(void* const* d_in, const int* in_sizes, int n_in,
                              void* d_out, int out_size) {
    const float* x     = (const float*)d_in[0];
    const int*   src   = (const int*)d_in[1];
    const int*   dst   = (const int*)d_in[2];
    const int*   etype = (const int*)d_in[3];
    const float* mask  = (const float*)d_in[4];
    const float* mask2 = (const float*)d_in[5];
    const float* lV = (const float*)d_in[6];
    const float* lC = (const float*)d_in[7];
    const float* lW = (const float*)d_in[8];
    const float* lB = (const float*)d_in[9];
    const float* gV = (const float*)d_in[10];
    const float* gC = (const float*)d_in[11];
    const float* gW = (const float*)d_in[12];
    const float* gB = (const float*)d_in[13];
    const float* w1 = (const float*)d_in[14];
    const float* b1 = (const float*)d_in[15];
    const float* w2 = (const float*)d_in[16];
    const float* b2 = (const float*)d_in[17];
    float* out = (float*)d_out;

    float *Hl, *Hg0, *Hg1, *Hg2;
    int* se2p;
    float2* wabp;
    cudaGetSymbolAddress((void**)&Hl,  g_Hl);
    cudaGetSymbolAddress((void**)&Hg0, g_Hg0);
    cudaGetSymbolAddress((void**)&Hg1, g_Hg1);
    cudaGetSymbolAddress((void**)&Hg2, g_Hg2);
    cudaGetSymbolAddress((void**)&se2p, g_se2);
    cudaGetSymbolAddress((void**)&wabp, g_wab);

    cudaFuncSetAttribute((const void*)gemm2_kernel<0, false>,
                         cudaFuncAttributeMaxDynamicSharedMemorySize, GEMM_SMEM);
    cudaFuncSetAttribute((const void*)gemm2_kernel<0, true>,
                         cudaFuncAttributeMaxDynamicSharedMemorySize, GEMM_SMEM);
    cudaFuncSetAttribute((const void*)gemm2_kernel<1, false>,
                         cudaFuncAttributeMaxDynamicSharedMemorySize, GEMM_SMEM);

    // prep + CSR + frontier in 4 launches (gather0 = 5th, gemm0 = 6th -> ncu captures gemm)
    k1_combo<<<COUNT_BLOCKS + PREP_BLOCKS, 256>>>(src, dst, lV, lW, lB, gV, gW, gB);
    k2_partial2<<<512, 256>>>();
    k34_write<<<512, 256>>>();
    k5_fill<<<EE / 256, 256>>>(src, dst, etype, mask, mask2, lC, gC);

    float* hg[3] = {Hg0, Hg1, Hg2};
    const float* h_in = x;
    for (int layer = 0; layer < LL; layer++) {
        float2* wl = wabp + (size_t)(2 * layer) * EE;
        float2* wg = wabp + (size_t)(2 * layer + 1) * EE;
        if (layer < LL - 1) {
            gather2_kernel<false><<<(NN * 16) / 256, 256>>>(h_in, se2p, wl, NN);
            gemm2_kernel<0, false><<<NN / 128, 256, GEMM_SMEM>>>(h_in, 2 * layer, Hl, NN);
            gather2_kernel<false><<<(NN * 16) / 256, 256>>>(Hl, se2p, wg, NN);
            gemm2_kernel<1, false><<<NN / 128, 256, GEMM_SMEM>>>(Hl, 2 * layer + 1, hg[layer], NN);
        } else {
            gather2_kernel<true><<<(NN * 16) / 256, 256>>>(h_in, se2p, wl, NN);
            gemm2_kernel<0, true><<<NN / 128, 256, GEMM_SMEM>>>(h_in, 2 * layer, Hl, NN);
            gather2_kernel<false><<<(BB * 16) / 256, 256>>>(Hl, se2p, wg, BB);
            gemm2_kernel<1, false><<<BB / 128, 256, GEMM_SMEM>>>(Hl, 2 * layer + 1, hg[layer], BB);
        }
        h_in = hg[layer];
    }

    mlp_kernel<<<BB, 128>>>(w1, b1, w2, b2, out);
}